// round 14
// baseline (speedup 1.0000x reference)
#include <cuda_runtime.h>
#include <cuda_bf16.h>
#include <mma.h>
#include <cstdint>

using namespace nvcuda;
typedef __nv_bfloat16 bf;

typedef wmma::fragment<wmma::accumulator, 16, 16, 16, float> AccF;
typedef wmma::fragment<wmma::matrix_a, 16, 16, 16, bf, wmma::row_major> AFrag;
typedef wmma::fragment<wmma::matrix_b, 16, 16, 16, bf, wmma::col_major> BCol;
typedef wmma::fragment<wmma::matrix_b, 16, 16, 16, bf, wmma::row_major> BRow;

// ---- device scratch ----
__device__ bf qwb[65536];            // q weights, pre-scaled by 0.125
__device__ bf kvwb[131072];
__device__ bf pwb[65536];
__device__ bf g_heat[33554432];      // proj output (BCHW bf16)
__device__ bf g_qkv[100663296];      // [tok 131072][768]: Q|K|V
__device__ bf g_o[33554432];         // attention output [tok][ch]
__device__ float g_keep[2048];
__device__ float g_ps[262144];       // [c 256][mblk 1024]
__device__ float g_pq[262144];
__device__ float g_scale[256];
__device__ float g_shift[256];

__device__ __forceinline__ uint32_t pk2(float a, float b) {
    __nv_bfloat162 h = __floats2bfloat162_rn(a, b);
    return *(uint32_t*)&h;
}

#define CPA16(dst, src) \
    asm volatile("cp.async.cg.shared.global [%0], [%1], 16;" \
                 :: "r"((unsigned)__cvta_generic_to_shared(dst)), "l"(src))
#define CPCOMMIT() asm volatile("cp.async.commit_group;" ::: "memory")
#define CPWAIT(n)  asm volatile("cp.async.wait_group %0;" :: "n"(n) : "memory")

// ================= weight convert (Q scale folded) =================
__global__ void wconv(const float* __restrict__ qw, const float* __restrict__ kvw,
                      const float* __restrict__ pw) {
    int i = blockIdx.x * 256 + threadIdx.x;
    if (i < 65536)  qwb[i]  = __float2bfloat16(qw[i] * 0.125f);
    if (i < 131072) kvwb[i] = __float2bfloat16(kvw[i]);
    if (i < 65536)  pwb[i]  = __float2bfloat16(pw[i]);
}

// ================= fused prep + QKV GEMM, A-resident =================
// grid (3, 1024): path 0=Q (A from feat), 1=K, 2=V (A from pre).
// Each CTA: build masked bf16 A tile (128 tok x 256 ch) in smem, 2 N-blocks.
// smem: As 67584 @0 ; Bs 2x18432 @67584 (sp f32 128x68 aliases) ; masks @104448
#define QF_MV 104448
#define QF_FM 104960
#define QF_PM 105472
#define QF_SMEM 105984
__global__ void __launch_bounds__(256)
qkv_fused2(const float* __restrict__ pre, const float* __restrict__ pmask,
           const float* __restrict__ feat, const float* __restrict__ fmask,
           const float* __restrict__ mask)
{
    extern __shared__ char sm[];
    bf* As = (bf*)sm;
    bf* Bs = (bf*)(sm + 67584);
    float* sp  = (float*)(sm + 67584);   // 128x68 f32 = 34816 <= 36864
    float* mv  = (float*)(sm + QF_MV);
    float* fmv = (float*)(sm + QF_FM);
    float* pmv = (float*)(sm + QF_PM);

    const int t = threadIdx.x, w = t >> 5;
    const int path = blockIdx.x, mblk = blockIdx.y;
    const int wi0 = mblk * 2;
    const int b = wi0 >> 8, h0 = ((wi0 >> 4) & 15) * 8, w0p = (wi0 & 15) * 8;
    const size_t tau0 = (size_t)mblk * 128;
    const int m0 = (w >> 2) * 64, n0 = (w & 3) * 32;

    // ---- masks for 128 tokens (2 windows) ----
    if (t < 128) {
        int win = t >> 6, loc = t & 63, r = loc >> 3, cp = loc & 7;
        int hh = h0 + r, ww = w0p + win * 8 + cp;
        float sh = 0.5f * hh - 0.25f, sw = 0.5f * ww - 0.25f;
        float fsh = floorf(sh), fsw = floorf(sw);
        int hi = (int)fsh, wx = (int)fsw;
        float fh = sh - fsh, fw = sw - fsw;
        int hA = min(max(hi, 0), 63), hB = min(max(hi + 1, 0), 63);
        int wA = min(max(wx, 0), 63), wB = min(max(wx + 1, 0), 63);
        const float* mb = mask + b * 4096;
        float fm = fmask[hh * 128 + ww];
        float v = (1.f - fh) * ((1.f - fw) * mb[hA * 64 + wA] + fw * mb[hA * 64 + wB])
                +        fh  * ((1.f - fw) * mb[hB * 64 + wA] + fw * mb[hB * 64 + wB]);
        mv[t]  = v * fm;
        fmv[t] = fm;
        pmv[t] = pmask[hh * 128 + ww];
    }
    __syncthreads();
    if (path == 0 && t < 2) {
        float mx = mv[t * 64];
        for (int i = 1; i < 64; i++) mx = fmaxf(mx, mv[t * 64 + i]);
        g_keep[wi0 + t] = (mx >= 0.2f) ? 1.f : 0.f;
    }

    // ---- build A tile: 8192 float4 over (ch, r, c4) ----
    const float* src = (path == 0) ? feat : pre;
#pragma unroll 4
    for (int it = 0; it < 32; it++) {
        int idx = t + it * 256;
        int ch = idx >> 5, rem = idx & 31;
        int r = rem >> 2, c4 = rem & 3;
        size_t g = ((size_t)(b * 256 + ch) * 128 + h0 + r) * 128 + w0p + c4 * 4;
        float4 v = *(const float4*)(src + g);
        float ve[4] = {v.x, v.y, v.z, v.w};
#pragma unroll
        for (int e = 0; e < 4; e++) {
            int col = c4 * 4 + e, win = col >> 3;
            int n = win * 64 + r * 8 + (col & 7);
            float s = (path == 0) ? ve[e] * fmv[n] : ve[e] * pmv[n] * mv[n];
            As[n * 264 + ch] = __float2bfloat16(s);
        }
    }

    const bf* Bbase = (path == 0) ? qwb : kvwb + (path - 1) * 65536;

#define B2LOAD(s, kc, Bb) do { \
    _Pragma("unroll") \
    for (int i_ = 0; i_ < 4; i_++) { \
        int idx_ = t + i_ * 256, row_ = idx_ >> 3, c8_ = (idx_ & 7) * 8; \
        CPA16(&Bs[(s) * 9216 + row_ * 72 + c8_], &(Bb)[(size_t)row_ * 256 + (kc) * 64 + c8_]); \
    } } while (0)

    for (int nb = 0; nb < 2; nb++) {
        const bf* Bb = Bbase + nb * 32768;
        const int nblk = path * 2 + nb;
        AccF acc[4][2];
#pragma unroll
        for (int i = 0; i < 4; i++)
#pragma unroll
            for (int j = 0; j < 2; j++) wmma::fill_fragment(acc[i][j], 0.f);

        __syncthreads();               // As ready / sp region free
        B2LOAD(0, 0, Bb);
        CPCOMMIT();
        for (int kc = 0; kc < 4; kc++) {
            int s = kc & 1;
            if (kc < 3) { B2LOAD(s ^ 1, kc + 1, Bb); CPCOMMIT(); CPWAIT(1); }
            else        { CPWAIT(0); }
            __syncthreads();
#pragma unroll
            for (int ks = 0; ks < 4; ks++) {
                AFrag a[4]; BCol bb[2];
#pragma unroll
                for (int i = 0; i < 4; i++)
                    wmma::load_matrix_sync(a[i], As + (m0 + i * 16) * 264 + kc * 64 + ks * 16, 264);
#pragma unroll
                for (int j = 0; j < 2; j++)
                    wmma::load_matrix_sync(bb[j], Bs + s * 9216 + (n0 + j * 16) * 72 + ks * 16, 72);
#pragma unroll
                for (int i = 0; i < 4; i++)
#pragma unroll
                    for (int j = 0; j < 2; j++) wmma::mma_sync(acc[i][j], a[i], bb[j], acc[i][j]);
            }
            __syncthreads();
        }
        // epilogue in two column halves (sp 128x68 aliases Bs)
#pragma unroll
        for (int half = 0; half < 2; half++) {
            if (((w & 3) >> 1) == half) {
#pragma unroll
                for (int i = 0; i < 4; i++)
#pragma unroll
                    for (int j = 0; j < 2; j++)
                        wmma::store_matrix_sync(sp + (m0 + i * 16) * 68 + (n0 - half * 64) + j * 16,
                                                acc[i][j], 68, wmma::mem_row_major);
            }
            __syncthreads();
#pragma unroll
            for (int i = 0; i < 4; i++) {
                int idx = t + i * 256, row = idx >> 3, c8 = (idx & 7) * 8;
                const float* s8 = sp + row * 68 + c8;
                uint4 v;
                v.x = pk2(s8[0], s8[1]); v.y = pk2(s8[2], s8[3]);
                v.z = pk2(s8[4], s8[5]); v.w = pk2(s8[6], s8[7]);
                *(uint4*)&g_qkv[(tau0 + row) * 768 + nblk * 128 + half * 64 + c8] = v;
            }
            __syncthreads();
        }
    }
}

// ================= per-window-per-head attention =================
// grid 8192: wi = blk>>2, head = blk&3 ; smem 45056
__global__ void __launch_bounds__(256)
attn()
{
    extern __shared__ char sm[];
    bf* qh = (bf*)sm;                 // 64 x 72 ; P aliases (Q dead after S)
    bf* ph = (bf*)sm;
    bf* kh = (bf*)(sm + 9216);
    bf* vh = (bf*)(sm + 18432);
    float* sp = (float*)(sm + 27648); // 64 x 68 f32

    const int t = threadIdx.x, w = t >> 5;
    const int h = blockIdx.x & 3;
    const size_t tau0 = (size_t)(blockIdx.x >> 2) * 64;
    const int mt = w & 3;

#pragma unroll
    for (int i = 0; i < 6; i++) {
        int idx = i * 256 + t;
        int tile = idx >> 9, rem = idx & 511;
        int r = rem >> 3, c8 = (rem & 7) * 8;
        bf* dst = (tile == 0) ? qh : (tile == 1) ? kh : vh;
        CPA16(&dst[r * 72 + c8], &g_qkv[(tau0 + r) * 768 + tile * 256 + h * 64 + c8]);
    }
    CPCOMMIT(); CPWAIT(0);
    __syncthreads();
    // S = Q K^T  (Q pre-scaled)
#pragma unroll
    for (int jj = 0; jj < 2; jj++) {
        int ng = (w >> 2) * 2 + jj;
        AccF c;
        wmma::fill_fragment(c, 0.f);
#pragma unroll
        for (int k = 0; k < 4; k++) {
            AFrag a; BCol bb;
            wmma::load_matrix_sync(a, qh + mt * 16 * 72 + k * 16, 72);
            wmma::load_matrix_sync(bb, kh + ng * 16 * 72 + k * 16, 72);
            wmma::mma_sync(c, a, bb, c);
        }
        wmma::store_matrix_sync(sp + mt * 16 * 68 + ng * 16, c, 68, wmma::mem_row_major);
    }
    __syncthreads();
    // softmax, 4 threads per row ; P overwrites Q region (Q dead)
    {
        int row = t >> 2, part = t & 3;
        const float* sr = sp + row * 68 + part * 16;
        float v[16], mx = -1e30f;
#pragma unroll
        for (int i = 0; i < 16; i++) { v[i] = sr[i]; mx = fmaxf(mx, v[i]); }
        mx = fmaxf(mx, __shfl_xor_sync(0xffffffffu, mx, 1));
        mx = fmaxf(mx, __shfl_xor_sync(0xffffffffu, mx, 2));
        float sum = 0.f;
#pragma unroll
        for (int i = 0; i < 16; i++) { v[i] = __expf(v[i] - mx); sum += v[i]; }
        sum += __shfl_xor_sync(0xffffffffu, sum, 1);
        sum += __shfl_xor_sync(0xffffffffu, sum, 2);
        float inv = 1.f / sum;
        uint32_t* d = (uint32_t*)(ph + row * 72 + part * 16);
#pragma unroll
        for (int i = 0; i < 8; i++) d[i] = pk2(v[2 * i] * inv, v[2 * i + 1] * inv);
    }
    __syncthreads();
    // O = P V
#pragma unroll
    for (int jj = 0; jj < 2; jj++) {
        int ng = (w >> 2) * 2 + jj;
        AccF c;
        wmma::fill_fragment(c, 0.f);
#pragma unroll
        for (int k = 0; k < 4; k++) {
            AFrag a; BRow bb;
            wmma::load_matrix_sync(a, ph + mt * 16 * 72 + k * 16, 72);
            wmma::load_matrix_sync(bb, vh + k * 16 * 72 + ng * 16, 72);
            wmma::mma_sync(c, a, bb, c);
        }
        wmma::store_matrix_sync(sp + mt * 16 * 68 + ng * 16, c, 68, wmma::mem_row_major);
    }
    __syncthreads();
#pragma unroll
    for (int i = 0; i < 2; i++) {
        int idx = i * 256 + t;
        int r = idx >> 3, c8 = (idx & 7) * 8;
        const float* s8 = sp + r * 68 + c8;
        uint4 v;
        v.x = pk2(s8[0], s8[1]); v.y = pk2(s8[2], s8[3]);
        v.z = pk2(s8[4], s8[5]); v.w = pk2(s8[6], s8[7]);
        *(uint4*)&g_o[(tau0 + r) * 256 + h * 64 + c8] = v;
    }
}

// ================= proj GEMM -> bf16 heat + BN partials =================
// grid (2, 1024); smem 86016
#define GS 9216
__global__ void __launch_bounds__(256)
proj_gemm(const float* __restrict__ feat, const float* __restrict__ fmask,
          const float* __restrict__ pb)
{
    extern __shared__ char sm[];
    bf* As = (bf*)sm;
    bf* Bs = (bf*)(sm + 36864);
    float* sp = (float*)sm;                  // col-major 128c x 136 (69632 B)
    float* bnS = (float*)(sm + 69632);
    float* bnQ = (float*)(sm + 69632 + 8192);

    const int t = threadIdx.x, w = t >> 5;
    const int nblk = blockIdx.x, mblk = blockIdx.y;
    const bf* Aab = g_o + (size_t)mblk * 128 * 256;
    const bf* Bb = pwb + nblk * 32768;

    AccF acc[4][2];
#pragma unroll
    for (int i = 0; i < 4; i++)
#pragma unroll
        for (int j = 0; j < 2; j++) wmma::fill_fragment(acc[i][j], 0.f);

#define PJ_LOAD(s, kc) do { \
    _Pragma("unroll") \
    for (int i_ = 0; i_ < 4; i_++) { \
        int idx_ = t + i_ * 256, row_ = idx_ >> 3, c8_ = (idx_ & 7) * 8; \
        CPA16(&As[(s) * GS + row_ * 72 + c8_], &Aab[(size_t)row_ * 256 + (kc) * 64 + c8_]); \
        CPA16(&Bs[(s) * GS + row_ * 72 + c8_], &Bb[(size_t)row_ * 256 + (kc) * 64 + c8_]); \
    } } while (0)

    PJ_LOAD(0, 0);
    CPCOMMIT();
    const int m0 = (w >> 2) * 64, n0 = (w & 3) * 32;
    for (int kc = 0; kc < 4; kc++) {
        int s = kc & 1;
        if (kc < 3) { PJ_LOAD(s ^ 1, kc + 1); CPCOMMIT(); CPWAIT(1); }
        else        { CPWAIT(0); }
        __syncthreads();
#pragma unroll
        for (int ks = 0; ks < 4; ks++) {
            AFrag a[4]; BCol b[2];
#pragma unroll
            for (int i = 0; i < 4; i++)
                wmma::load_matrix_sync(a[i], As + s * GS + (m0 + i * 16) * 72 + ks * 16, 72);
#pragma unroll
            for (int j = 0; j < 2; j++)
                wmma::load_matrix_sync(b[j], Bs + s * GS + (n0 + j * 16) * 72 + ks * 16, 72);
#pragma unroll
            for (int i = 0; i < 4; i++)
#pragma unroll
                for (int j = 0; j < 2; j++) wmma::mma_sync(acc[i][j], a[i], b[j], acc[i][j]);
        }
        __syncthreads();
    }
#pragma unroll
    for (int i = 0; i < 4; i++)
#pragma unroll
        for (int j = 0; j < 2; j++)
            wmma::store_matrix_sync(sp + (n0 + j * 16) * 136 + m0 + i * 16, acc[i][j],
                                    136, wmma::mem_col_major);
    __syncthreads();

    const int wi0 = mblk * 2;
    const float keep0 = g_keep[wi0], keep1 = g_keep[wi0 + 1];
    const int c0 = nblk * 128;
#pragma unroll
    for (int iter = 0; iter < 8; iter++) {
        int idx = iter * 256 + t;
        int cl = idx >> 4, wr = idx & 15, win = wr >> 3, r = wr & 7;
        int c = c0 + cl;
        int wi = wi0 + win;
        int b = wi >> 8, h0 = ((wi >> 4) & 15) * 8, w0 = (wi & 15) * 8;
        int hh = h0 + r;
        size_t g = ((size_t)(b * 256 + c) * 128 + hh) * 128 + w0;
        float keep = win ? keep1 : keep0;
        float bias = pb[c];
        const float* srow = sp + cl * 136 + win * 64 + r * 8;
        const float* fm = fmask + hh * 128 + w0;
        float s = 0.f, q = 0.f;
        bf hb[8];
#pragma unroll
        for (int e = 0; e < 8; e++) {
            hb[e] = __float2bfloat16((srow[e] + bias) * keep);
            float val = __bfloat162float(hb[e]) + feat[g + e] * fm[e];
            s += val; q += val * val;
        }
        *(uint4*)&g_heat[g] = *(uint4*)hb;
        bnS[cl * 16 + wr] = s;
        bnQ[cl * 16 + wr] = q;
    }
    __syncthreads();
    if (t < 128) {
        float s = 0.f, q = 0.f;
#pragma unroll
        for (int m = 0; m < 16; m++) { s += bnS[t * 16 + m]; q += bnQ[t * 16 + m]; }
        g_ps[(size_t)(c0 + t) * 1024 + mblk] = s;
        g_pq[(size_t)(c0 + t) * 1024 + mblk] = q;
    }
}

// ================= BN finalize + apply =================
__global__ void bn_fin(const float* __restrict__ gamma, const float* __restrict__ beta) {
    __shared__ float rs[256], rq[256];
    const int c = blockIdx.x, t = threadIdx.x;
    float s = 0.f, q = 0.f;
    for (int i = t; i < 1024; i += 256) {
        s += g_ps[c * 1024 + i];
        q += g_pq[c * 1024 + i];
    }
    rs[t] = s; rq[t] = q;
    __syncthreads();
    for (int o = 128; o > 0; o >>= 1) {
        if (t < o) { rs[t] += rs[t + o]; rq[t] += rq[t + o]; }
        __syncthreads();
    }
    if (t == 0) {
        const float inv_n = 1.f / 131072.f;
        float mean = rs[0] * inv_n;
        float var = rq[0] * inv_n - mean * mean;
        float sc = gamma[c] * rsqrtf(var + 1e-5f);
        g_scale[c] = sc;
        g_shift[c] = beta[c] - mean * sc;
    }
}

__global__ void bn_apply(const float* __restrict__ feat, const float* __restrict__ fmask,
                         float* __restrict__ out) {
    int i = blockIdx.x * blockDim.x + threadIdx.x;   // over 8,388,608 float4
    int c = (i >> 12) & 255;
    int p = i & 4095;
    float sc = g_scale[c], sh = g_shift[c];
    float4 fm = ((const float4*)fmask)[p];
    float4 f  = ((const float4*)feat)[i];
    uint2 hu = ((const uint2*)g_heat)[i];
    __nv_bfloat162 h01 = *(__nv_bfloat162*)&hu.x;
    __nv_bfloat162 h23 = *(__nv_bfloat162*)&hu.y;
    float4 v;
    v.x = (__bfloat162float(h01.x) + f.x * fm.x) * sc + sh;
    v.y = (__bfloat162float(h01.y) + f.y * fm.y) * sc + sh;
    v.z = (__bfloat162float(h23.x) + f.z * fm.z) * sc + sh;
    v.w = (__bfloat162float(h23.y) + f.w * fm.w) * sc + sh;
    ((float4*)out)[i] = v;
}

// ================= launch =================
extern "C" void kernel_launch(void* const* d_in, const int* in_sizes, int n_in,
                              void* d_out, int out_size)
{
    const float* pre   = (const float*)d_in[0];
    const float* pmask = (const float*)d_in[1];
    const float* feat  = (const float*)d_in[2];
    const float* fmask = (const float*)d_in[3];
    const float* mask  = (const float*)d_in[4];
    const float* qw    = (const float*)d_in[5];
    const float* kvw   = (const float*)d_in[6];
    const float* pw    = (const float*)d_in[7];
    const float* pb    = (const float*)d_in[8];
    const float* gamma = (const float*)d_in[9];
    const float* beta  = (const float*)d_in[10];
    float* out = (float*)d_out;

    cudaFuncSetAttribute(qkv_fused2, cudaFuncAttributeMaxDynamicSharedMemorySize, QF_SMEM);
    cudaFuncSetAttribute(attn, cudaFuncAttributeMaxDynamicSharedMemorySize, 45056);
    cudaFuncSetAttribute(proj_gemm, cudaFuncAttributeMaxDynamicSharedMemorySize, 86016);

    wconv<<<512, 256>>>(qw, kvw, pw);
    qkv_fused2<<<dim3(3, 1024), 256, QF_SMEM>>>(pre, pmask, feat, fmask, mask);
    attn<<<8192, 256, 45056>>>();
    proj_gemm<<<dim3(2, 1024), 256, 86016>>>(feat, fmask, pb);
    bn_fin<<<256, 256>>>(gamma, beta);
    bn_apply<<<32768, 256>>>(feat, fmask, out);
}

// round 15
// speedup vs baseline: 1.0736x; 1.0736x over previous
#include <cuda_runtime.h>
#include <cuda_bf16.h>
#include <mma.h>
#include <cstdint>

using namespace nvcuda;
typedef __nv_bfloat16 bf;

typedef wmma::fragment<wmma::accumulator, 16, 16, 16, float> AccF;
typedef wmma::fragment<wmma::matrix_a, 16, 16, 16, bf, wmma::row_major> AFrag;
typedef wmma::fragment<wmma::matrix_b, 16, 16, 16, bf, wmma::col_major> BCol;
typedef wmma::fragment<wmma::matrix_b, 16, 16, 16, bf, wmma::row_major> BRow;

// ---- device scratch ----
__device__ bf qwb[65536];            // q weights, pre-scaled by 0.125
__device__ bf kvwb[131072];
__device__ bf pwb[65536];
__device__ bf g_x1[33554432];        // [tok][ch] ; reused as g_heat (BCHW bf16) after qkv
__device__ bf g_tp[33554432];
__device__ bf g_qkv[100663296];      // [tok][768]: Q|K|V
__device__ bf g_o[33554432];         // attention output [tok][ch]
__device__ float g_keep[2048];
__device__ float g_ps[262144];       // [c 256][mblk 1024]
__device__ float g_pq[262144];
__device__ float g_scale[256];
__device__ float g_shift[256];

__device__ __forceinline__ uint32_t pk2(float a, float b) {
    __nv_bfloat162 h = __floats2bfloat162_rn(a, b);
    return *(uint32_t*)&h;
}

#define CPA16(dst, src) \
    asm volatile("cp.async.cg.shared.global [%0], [%1], 16;" \
                 :: "r"((unsigned)__cvta_generic_to_shared(dst)), "l"(src))
#define CPCOMMIT() asm volatile("cp.async.commit_group;" ::: "memory")
#define CPWAIT(n)  asm volatile("cp.async.wait_group %0;" :: "n"(n) : "memory")

// ================= weight convert (Q scale folded) =================
__global__ void wconv(const float* __restrict__ qw, const float* __restrict__ kvw,
                      const float* __restrict__ pw) {
    int i = blockIdx.x * 256 + threadIdx.x;
    if (i < 65536)  qwb[i]  = __float2bfloat16(qw[i] * 0.125f);
    if (i < 131072) kvwb[i] = __float2bfloat16(kvw[i]);
    if (i < 65536)  pwb[i]  = __float2bfloat16(pw[i]);
}

// ================= prep: masked inputs -> token-major bf16 =================
__global__ void __launch_bounds__(256)
prep(const float* __restrict__ pre, const float* __restrict__ pmask,
     const float* __restrict__ feat, const float* __restrict__ fmask,
     const float* __restrict__ mask)
{
    extern __shared__ char sm[];
    bf* x1s = (bf*)sm;                       // 64 x 264
    bf* tps = (bf*)(sm + 33792);
    float* mv  = (float*)(sm + 67584);
    float* fmv = (float*)(sm + 67840);
    float* pmv = (float*)(sm + 68096);

    const int t = threadIdx.x, wi = blockIdx.x;
    const int b = wi >> 8, h0 = ((wi >> 4) & 15) * 8, w0 = (wi & 15) * 8;

    if (t < 64) {   // bilinear 64->128 half-pixel clamp
        int r = t >> 3, cp = t & 7;
        int hh = h0 + r, ww = w0 + cp;
        float sh = 0.5f * hh - 0.25f, sw = 0.5f * ww - 0.25f;
        float fsh = floorf(sh), fsw = floorf(sw);
        int hi = (int)fsh, wx = (int)fsw;
        float fh = sh - fsh, fw = sw - fsw;
        int hA = min(max(hi, 0), 63), hB = min(max(hi + 1, 0), 63);
        int wA = min(max(wx, 0), 63), wB = min(max(wx + 1, 0), 63);
        const float* mb = mask + b * 4096;
        float fm = fmask[hh * 128 + ww];
        float v = (1.f - fh) * ((1.f - fw) * mb[hA * 64 + wA] + fw * mb[hA * 64 + wB])
                +        fh  * ((1.f - fw) * mb[hB * 64 + wA] + fw * mb[hB * 64 + wB]);
        mv[t] = v * fm;
        fmv[t] = fm;
        pmv[t] = pmask[hh * 128 + ww];
    }
    __syncthreads();
    if (t == 0) {
        float mx = mv[0];
        for (int i = 1; i < 64; i++) mx = fmaxf(mx, mv[i]);
        g_keep[wi] = (mx >= 0.2f) ? 1.f : 0.f;
    }

#pragma unroll 4
    for (int it = 0; it < 64; it++) {
        int ch = (t >> 3) + (it & 7) * 32;
        int r = it >> 3, cp = t & 7, n = r * 8 + cp;
        size_t g = ((size_t)(b * 256 + ch) * 128 + h0 + r) * 128 + w0 + cp;
        x1s[n * 264 + ch] = __float2bfloat16(feat[g] * fmv[n]);
        tps[n * 264 + ch] = __float2bfloat16(pre[g] * pmv[n] * mv[n]);
    }
    __syncthreads();
#pragma unroll
    for (int it = 0; it < 8; it++) {
        int idx = it * 256 + t;
        int n = idx >> 5, u = idx & 31;
        size_t d = ((size_t)wi * 64 + n) * 256 + u * 8;
        *(uint4*)&g_x1[d] = *(const uint4*)&x1s[n * 264 + u * 8];
        *(uint4*)&g_tp[d] = *(const uint4*)&tps[n * 264 + u * 8];
    }
}

// ================= QKV GEMM, A-resident =================
// grid (2, 1024): x=path (0: Q from g_x1, 2 nblks; 1: KV from g_tp, 4 nblks)
#define Q2_SMEM 104448
__global__ void __launch_bounds__(256)
qkv_gemm2()
{
    extern __shared__ char sm[];
    bf* As = (bf*)sm;
    bf* Bs = (bf*)(sm + 67584);
    float* sp = (float*)(sm + 67584);     // 128 x 68 f32 = 34816 <= 36864

    const int t = threadIdx.x, w = t >> 5;
    const int path = blockIdx.x, mblk = blockIdx.y;
    const bf* Aab = (path ? g_tp : g_x1) + (size_t)mblk * 128 * 256;
    const bf* Bbase = path ? kvwb : qwb;
    const int nbc = path ? 4 : 2;
    const size_t tau0 = (size_t)mblk * 128;
    const int m0 = (w >> 2) * 64, n0 = (w & 3) * 32;

#pragma unroll
    for (int it = 0; it < 16; it++) {
        int idx = t + it * 256, row = idx >> 5, u = (idx & 31) * 8;
        CPA16(&As[row * 264 + u], &Aab[(size_t)row * 256 + u]);
    }
    CPCOMMIT();

#define B2LOAD(s, kc, Bb) do { \
    _Pragma("unroll") \
    for (int i_ = 0; i_ < 4; i_++) { \
        int idx_ = t + i_ * 256, row_ = idx_ >> 3, c8_ = (idx_ & 7) * 8; \
        CPA16(&Bs[(s) * 9216 + row_ * 72 + c8_], &(Bb)[(size_t)row_ * 256 + (kc) * 64 + c8_]); \
    } } while (0)

    for (int nb = 0; nb < nbc; nb++) {
        const bf* Bb = Bbase + nb * 32768;
        const int nblk = path ? 2 + nb : nb;
        AccF acc[4][2];
#pragma unroll
        for (int i = 0; i < 4; i++)
#pragma unroll
            for (int j = 0; j < 2; j++) wmma::fill_fragment(acc[i][j], 0.f);

        __syncthreads();
        B2LOAD(0, 0, Bb);
        CPCOMMIT();
        for (int kc = 0; kc < 4; kc++) {
            int s = kc & 1;
            if (kc < 3) { B2LOAD(s ^ 1, kc + 1, Bb); CPCOMMIT(); CPWAIT(1); }
            else        { CPWAIT(0); }
            __syncthreads();
#pragma unroll
            for (int ks = 0; ks < 4; ks++) {
                AFrag a[4]; BCol b[2];
#pragma unroll
                for (int i = 0; i < 4; i++)
                    wmma::load_matrix_sync(a[i], As + (m0 + i * 16) * 264 + kc * 64 + ks * 16, 264);
#pragma unroll
                for (int j = 0; j < 2; j++)
                    wmma::load_matrix_sync(b[j], Bs + s * 9216 + (n0 + j * 16) * 72 + ks * 16, 72);
#pragma unroll
                for (int i = 0; i < 4; i++)
#pragma unroll
                    for (int j = 0; j < 2; j++) wmma::mma_sync(acc[i][j], a[i], b[j], acc[i][j]);
            }
            __syncthreads();
        }
#pragma unroll
        for (int half = 0; half < 2; half++) {
            if (((w & 3) >> 1) == half) {
#pragma unroll
                for (int i = 0; i < 4; i++)
#pragma unroll
                    for (int j = 0; j < 2; j++)
                        wmma::store_matrix_sync(sp + (m0 + i * 16) * 68 + (n0 - half * 64) + j * 16,
                                                acc[i][j], 68, wmma::mem_row_major);
            }
            __syncthreads();
#pragma unroll
            for (int i = 0; i < 4; i++) {
                int idx = t + i * 256, row = idx >> 3, c8 = (idx & 7) * 8;
                const float* s8 = sp + row * 68 + c8;
                uint4 v;
                v.x = pk2(s8[0], s8[1]); v.y = pk2(s8[2], s8[3]);
                v.z = pk2(s8[4], s8[5]); v.w = pk2(s8[6], s8[7]);
                *(uint4*)&g_qkv[(tau0 + row) * 768 + nblk * 128 + half * 64 + c8] = v;
            }
            __syncthreads();
        }
    }
}

// ================= per-(window,head) attention =================
// grid 8192: wi = blk>>2, head = blk&3 ; smem 45056
__global__ void __launch_bounds__(256)
attn()
{
    extern __shared__ char sm[];
    bf* qh = (bf*)sm;                 // 64 x 72 ; P aliases (Q dead after S)
    bf* ph = (bf*)sm;
    bf* kh = (bf*)(sm + 9216);
    bf* vh = (bf*)(sm + 18432);
    float* sp = (float*)(sm + 27648); // 64 x 68 f32

    const int t = threadIdx.x, w = t >> 5;
    const int h = blockIdx.x & 3;
    const size_t tau0 = (size_t)(blockIdx.x >> 2) * 64;
    const int mt = w & 3;

#pragma unroll
    for (int i = 0; i < 6; i++) {
        int idx = i * 256 + t;
        int tile = idx >> 9, rem = idx & 511;
        int r = rem >> 3, c8 = (rem & 7) * 8;
        bf* dst = (tile == 0) ? qh : (tile == 1) ? kh : vh;
        CPA16(&dst[r * 72 + c8], &g_qkv[(tau0 + r) * 768 + tile * 256 + h * 64 + c8]);
    }
    CPCOMMIT(); CPWAIT(0);
    __syncthreads();
#pragma unroll
    for (int jj = 0; jj < 2; jj++) {
        int ng = (w >> 2) * 2 + jj;
        AccF c;
        wmma::fill_fragment(c, 0.f);
#pragma unroll
        for (int k = 0; k < 4; k++) {
            AFrag a; BCol bb;
            wmma::load_matrix_sync(a, qh + mt * 16 * 72 + k * 16, 72);
            wmma::load_matrix_sync(bb, kh + ng * 16 * 72 + k * 16, 72);
            wmma::mma_sync(c, a, bb, c);
        }
        wmma::store_matrix_sync(sp + mt * 16 * 68 + ng * 16, c, 68, wmma::mem_row_major);
    }
    __syncthreads();
    {
        int row = t >> 2, part = t & 3;
        const float* sr = sp + row * 68 + part * 16;
        float v[16], mx = -1e30f;
#pragma unroll
        for (int i = 0; i < 16; i++) { v[i] = sr[i]; mx = fmaxf(mx, v[i]); }
        mx = fmaxf(mx, __shfl_xor_sync(0xffffffffu, mx, 1));
        mx = fmaxf(mx, __shfl_xor_sync(0xffffffffu, mx, 2));
        float sum = 0.f;
#pragma unroll
        for (int i = 0; i < 16; i++) { v[i] = __expf(v[i] - mx); sum += v[i]; }
        sum += __shfl_xor_sync(0xffffffffu, sum, 1);
        sum += __shfl_xor_sync(0xffffffffu, sum, 2);
        float inv = 1.f / sum;
        uint32_t* d = (uint32_t*)(ph + row * 72 + part * 16);
#pragma unroll
        for (int i = 0; i < 8; i++) d[i] = pk2(v[2 * i] * inv, v[2 * i + 1] * inv);
    }
    __syncthreads();
#pragma unroll
    for (int jj = 0; jj < 2; jj++) {
        int ng = (w >> 2) * 2 + jj;
        AccF c;
        wmma::fill_fragment(c, 0.f);
#pragma unroll
        for (int k = 0; k < 4; k++) {
            AFrag a; BRow bb;
            wmma::load_matrix_sync(a, ph + mt * 16 * 72 + k * 16, 72);
            wmma::load_matrix_sync(bb, vh + k * 16 * 72 + ng * 16, 72);
            wmma::mma_sync(c, a, bb, c);
        }
        wmma::store_matrix_sync(sp + mt * 16 * 68 + ng * 16, c, 68, wmma::mem_row_major);
    }
    __syncthreads();
#pragma unroll
    for (int i = 0; i < 2; i++) {
        int idx = i * 256 + t;
        int r = idx >> 3, c8 = (idx & 7) * 8;
        const float* s8 = sp + r * 68 + c8;
        uint4 v;
        v.x = pk2(s8[0], s8[1]); v.y = pk2(s8[2], s8[3]);
        v.z = pk2(s8[4], s8[5]); v.w = pk2(s8[6], s8[7]);
        *(uint4*)&g_o[(tau0 + r) * 256 + h * 64 + c8] = v;
    }
}

// ================= proj GEMM (N=64/CTA, occ 3) -> bf16 heat + BN =================
// grid (4, 1024): nblk = 64-channel block, mblk = 128-token block
// smem: As 2x(128x72) = 36864 @0 ; Bs 2x(64x72) = 18432 @36864 -> 55296
// epilogue aliases: sp 64x136 f32 = 34816 @0 ; bnS @34816 (4096) ; bnQ @38912 (4096)
#define PJ_SMEM 55296
__global__ void __launch_bounds__(256, 3)
proj_gemm(const float* __restrict__ feat, const float* __restrict__ fmask,
          const float* __restrict__ pb)
{
    extern __shared__ char sm[];
    bf* As = (bf*)sm;
    bf* Bs = (bf*)(sm + 36864);
    float* sp = (float*)sm;
    float* bnS = (float*)(sm + 34816);
    float* bnQ = (float*)(sm + 38912);

    const int t = threadIdx.x, w = t >> 5;
    const int nblk = blockIdx.x, mblk = blockIdx.y;
    const bf* Aab = g_o + (size_t)mblk * 128 * 256;
    const bf* Bb = pwb + nblk * 16384;            // 64 rows x 256

    AccF acc[4];
#pragma unroll
    for (int j = 0; j < 4; j++) wmma::fill_fragment(acc[j], 0.f);

#define PJ4_LOAD(s, kc) do { \
    _Pragma("unroll") \
    for (int i_ = 0; i_ < 4; i_++) { \
        int idx_ = t + i_ * 256, row_ = idx_ >> 3, c8_ = (idx_ & 7) * 8; \
        CPA16(&As[(s) * 9216 + row_ * 72 + c8_], &Aab[(size_t)row_ * 256 + (kc) * 64 + c8_]); \
    } \
    { \
        int idx_ = t, row_ = idx_ >> 3, c8_ = (idx_ & 7) * 8; \
        if (row_ < 64) \
            CPA16(&Bs[(s) * 4608 + row_ * 72 + c8_], &Bb[(size_t)row_ * 256 + (kc) * 64 + c8_]); \
    } \
    { \
        int idx_ = t + 256, row_ = idx_ >> 3, c8_ = (idx_ & 7) * 8; \
        CPA16(&Bs[(s) * 4608 + row_ * 72 + c8_], &Bb[(size_t)row_ * 256 + (kc) * 64 + c8_]); \
    } } while (0)

    PJ4_LOAD(0, 0);
    CPCOMMIT();
    const int mt = w;                     // 8 warps x 16 rows = 128
    for (int kc = 0; kc < 4; kc++) {
        int s = kc & 1;
        if (kc < 3) { PJ4_LOAD(s ^ 1, kc + 1); CPCOMMIT(); CPWAIT(1); }
        else        { CPWAIT(0); }
        __syncthreads();
#pragma unroll
        for (int ks = 0; ks < 4; ks++) {
            AFrag a;
            wmma::load_matrix_sync(a, As + s * 9216 + mt * 16 * 72 + ks * 16, 72);
#pragma unroll
            for (int j = 0; j < 4; j++) {
                BCol bb;
                wmma::load_matrix_sync(bb, Bs + s * 4608 + j * 16 * 72 + ks * 16, 72);
                wmma::mma_sync(acc[j], a, bb, acc[j]);
            }
        }
        __syncthreads();
    }
    // stage accumulators col-major: sp[c * 136 + m], c in [0,64)
#pragma unroll
    for (int j = 0; j < 4; j++)
        wmma::store_matrix_sync(sp + j * 16 * 136 + mt * 16, acc[j], 136, wmma::mem_col_major);
    __syncthreads();

    const int wi0 = mblk * 2;
    const float keep0 = g_keep[wi0], keep1 = g_keep[wi0 + 1];
    const int c0 = nblk * 64;
#pragma unroll
    for (int iter = 0; iter < 4; iter++) {
        int idx = iter * 256 + t;
        int cl = idx >> 4, wr = idx & 15, win = wr >> 3, r = wr & 7;
        int c = c0 + cl;
        int wi = wi0 + win;
        int b = wi >> 8, h0 = ((wi >> 4) & 15) * 8, w0 = (wi & 15) * 8;
        int hh = h0 + r;
        size_t g = ((size_t)(b * 256 + c) * 128 + hh) * 128 + w0;
        float keep = win ? keep1 : keep0;
        float bias = pb[c];
        const float* srow = sp + cl * 136 + win * 64 + r * 8;
        const float* fm = fmask + hh * 128 + w0;
        float s = 0.f, q = 0.f;
        bf hb[8];
#pragma unroll
        for (int e = 0; e < 8; e++) {
            hb[e] = __float2bfloat16((srow[e] + bias) * keep);
            float val = __bfloat162float(hb[e]) + feat[g + e] * fm[e];
            s += val; q += val * val;
        }
        *(uint4*)&g_x1[g] = *(uint4*)hb;   // g_x1 reused as heat (BCHW bf16)
        bnS[cl * 16 + wr] = s;
        bnQ[cl * 16 + wr] = q;
    }
    __syncthreads();
    if (t < 64) {
        float s = 0.f, q = 0.f;
#pragma unroll
        for (int m = 0; m < 16; m++) { s += bnS[t * 16 + m]; q += bnQ[t * 16 + m]; }
        g_ps[(size_t)(c0 + t) * 1024 + mblk] = s;
        g_pq[(size_t)(c0 + t) * 1024 + mblk] = q;
    }
}

// ================= BN finalize + apply =================
__global__ void bn_fin(const float* __restrict__ gamma, const float* __restrict__ beta) {
    __shared__ float rs[256], rq[256];
    const int c = blockIdx.x, t = threadIdx.x;
    float s = 0.f, q = 0.f;
    for (int i = t; i < 1024; i += 256) {
        s += g_ps[c * 1024 + i];
        q += g_pq[c * 1024 + i];
    }
    rs[t] = s; rq[t] = q;
    __syncthreads();
    for (int o = 128; o > 0; o >>= 1) {
        if (t < o) { rs[t] += rs[t + o]; rq[t] += rq[t + o]; }
        __syncthreads();
    }
    if (t == 0) {
        const float inv_n = 1.f / 131072.f;
        float mean = rs[0] * inv_n;
        float var = rq[0] * inv_n - mean * mean;
        float sc = gamma[c] * rsqrtf(var + 1e-5f);
        g_scale[c] = sc;
        g_shift[c] = beta[c] - mean * sc;
    }
}

__global__ void bn_apply(const float* __restrict__ feat, const float* __restrict__ fmask,
                         float* __restrict__ out) {
    int i = blockIdx.x * blockDim.x + threadIdx.x;
    int c = (i >> 12) & 255;
    int p = i & 4095;
    float sc = g_scale[c], sh = g_shift[c];
    float4 fm = ((const float4*)fmask)[p];
    float4 f  = ((const float4*)feat)[i];
    uint2 hu = ((const uint2*)g_x1)[i];
    __nv_bfloat162 h01 = *(__nv_bfloat162*)&hu.x;
    __nv_bfloat162 h23 = *(__nv_bfloat162*)&hu.y;
    float4 v;
    v.x = (__bfloat162float(h01.x) + f.x * fm.x) * sc + sh;
    v.y = (__bfloat162float(h01.y) + f.y * fm.y) * sc + sh;
    v.z = (__bfloat162float(h23.x) + f.z * fm.z) * sc + sh;
    v.w = (__bfloat162float(h23.y) + f.w * fm.w) * sc + sh;
    ((float4*)out)[i] = v;
}

// ================= launch =================
extern "C" void kernel_launch(void* const* d_in, const int* in_sizes, int n_in,
                              void* d_out, int out_size)
{
    const float* pre   = (const float*)d_in[0];
    const float* pmask = (const float*)d_in[1];
    const float* feat  = (const float*)d_in[2];
    const float* fmask = (const float*)d_in[3];
    const float* mask  = (const float*)d_in[4];
    const float* qw    = (const float*)d_in[5];
    const float* kvw   = (const float*)d_in[6];
    const float* pw    = (const float*)d_in[7];
    const float* pb    = (const float*)d_in[8];
    const float* gamma = (const float*)d_in[9];
    const float* beta  = (const float*)d_in[10];
    float* out = (float*)d_out;

    cudaFuncSetAttribute(prep, cudaFuncAttributeMaxDynamicSharedMemorySize, 68352);
    cudaFuncSetAttribute(qkv_gemm2, cudaFuncAttributeMaxDynamicSharedMemorySize, Q2_SMEM);
    cudaFuncSetAttribute(attn, cudaFuncAttributeMaxDynamicSharedMemorySize, 45056);
    cudaFuncSetAttribute(proj_gemm, cudaFuncAttributeMaxDynamicSharedMemorySize, PJ_SMEM);

    wconv<<<512, 256>>>(qw, kvw, pw);
    prep<<<2048, 256, 68352>>>(pre, pmask, feat, fmask, mask);
    qkv_gemm2<<<dim3(2, 1024), 256, Q2_SMEM>>>();
    attn<<<8192, 256, 45056>>>();
    proj_gemm<<<dim3(4, 1024), 256, PJ_SMEM>>>(feat, fmask, pb);
    bn_fin<<<256, 256>>>(gamma, beta);
    bn_apply<<<32768, 256>>>(feat, fmask, out);
}

// round 16
// speedup vs baseline: 1.1342x; 1.0565x over previous
#include <cuda_runtime.h>
#include <cuda_bf16.h>
#include <mma.h>
#include <cstdint>

using namespace nvcuda;
typedef __nv_bfloat16 bf;

typedef wmma::fragment<wmma::accumulator, 16, 16, 16, float> AccF;
typedef wmma::fragment<wmma::matrix_a, 16, 16, 16, bf, wmma::row_major> AFrag;
typedef wmma::fragment<wmma::matrix_b, 16, 16, 16, bf, wmma::col_major> BCol;
typedef wmma::fragment<wmma::matrix_b, 16, 16, 16, bf, wmma::row_major> BRow;

// ---- device scratch ----
__device__ bf qwb[65536];            // q weights, pre-scaled by 0.125
__device__ bf kvwb[131072];
__device__ bf pwb[65536];
__device__ bf g_x1[33554432];        // [tok][ch] ; reused as g_heat (BCHW bf16) after qkv
__device__ bf g_tp[33554432];
__device__ bf g_qkv[100663296];      // [tok][768]: Q|K|V
__device__ bf g_o[33554432];         // attention output [tok][ch]
__device__ float g_keep[2048];
__device__ float g_ps[262144];       // [c 256][mblk 1024]
__device__ float g_pq[262144];
__device__ float g_scale[256];
__device__ float g_shift[256];

__device__ __forceinline__ uint32_t pk2(float a, float b) {
    __nv_bfloat162 h = __floats2bfloat162_rn(a, b);
    return *(uint32_t*)&h;
}

#define CPA16(dst, src) \
    asm volatile("cp.async.cg.shared.global [%0], [%1], 16;" \
                 :: "r"((unsigned)__cvta_generic_to_shared(dst)), "l"(src))
#define CPCOMMIT() asm volatile("cp.async.commit_group;" ::: "memory")
#define CPWAIT(n)  asm volatile("cp.async.wait_group %0;" :: "n"(n) : "memory")

// ================= weight convert (Q scale folded) =================
__global__ void wconv(const float* __restrict__ qw, const float* __restrict__ kvw,
                      const float* __restrict__ pw) {
    int i = blockIdx.x * 256 + threadIdx.x;
    if (i < 65536)  qwb[i]  = __float2bfloat16(qw[i] * 0.125f);
    if (i < 131072) kvwb[i] = __float2bfloat16(kvw[i]);
    if (i < 65536)  pwb[i]  = __float2bfloat16(pw[i]);
}

// ================= prep: masked inputs -> token-major bf16 =================
__global__ void __launch_bounds__(256)
prep(const float* __restrict__ pre, const float* __restrict__ pmask,
     const float* __restrict__ feat, const float* __restrict__ fmask,
     const float* __restrict__ mask)
{
    extern __shared__ char sm[];
    bf* x1s = (bf*)sm;                       // 64 x 264
    bf* tps = (bf*)(sm + 33792);
    float* mv  = (float*)(sm + 67584);
    float* fmv = (float*)(sm + 67840);
    float* pmv = (float*)(sm + 68096);

    const int t = threadIdx.x, wi = blockIdx.x;
    const int b = wi >> 8, h0 = ((wi >> 4) & 15) * 8, w0 = (wi & 15) * 8;

    if (t < 64) {   // bilinear 64->128 half-pixel clamp
        int r = t >> 3, cp = t & 7;
        int hh = h0 + r, ww = w0 + cp;
        float sh = 0.5f * hh - 0.25f, sw = 0.5f * ww - 0.25f;
        float fsh = floorf(sh), fsw = floorf(sw);
        int hi = (int)fsh, wx = (int)fsw;
        float fh = sh - fsh, fw = sw - fsw;
        int hA = min(max(hi, 0), 63), hB = min(max(hi + 1, 0), 63);
        int wA = min(max(wx, 0), 63), wB = min(max(wx + 1, 0), 63);
        const float* mb = mask + b * 4096;
        float fm = fmask[hh * 128 + ww];
        float v = (1.f - fh) * ((1.f - fw) * mb[hA * 64 + wA] + fw * mb[hA * 64 + wB])
                +        fh  * ((1.f - fw) * mb[hB * 64 + wA] + fw * mb[hB * 64 + wB]);
        mv[t] = v * fm;
        fmv[t] = fm;
        pmv[t] = pmask[hh * 128 + ww];
    }
    __syncthreads();
    if (t == 0) {
        float mx = mv[0];
        for (int i = 1; i < 64; i++) mx = fmaxf(mx, mv[i]);
        g_keep[wi] = (mx >= 0.2f) ? 1.f : 0.f;
    }

#pragma unroll 4
    for (int it = 0; it < 64; it++) {
        int ch = (t >> 3) + (it & 7) * 32;
        int r = it >> 3, cp = t & 7, n = r * 8 + cp;
        size_t g = ((size_t)(b * 256 + ch) * 128 + h0 + r) * 128 + w0 + cp;
        x1s[n * 264 + ch] = __float2bfloat16(feat[g] * fmv[n]);
        tps[n * 264 + ch] = __float2bfloat16(pre[g] * pmv[n] * mv[n]);
    }
    __syncthreads();
#pragma unroll
    for (int it = 0; it < 8; it++) {
        int idx = it * 256 + t;
        int n = idx >> 5, u = idx & 31;
        size_t d = ((size_t)wi * 64 + n) * 256 + u * 8;
        *(uint4*)&g_x1[d] = *(const uint4*)&x1s[n * 264 + u * 8];
        *(uint4*)&g_tp[d] = *(const uint4*)&tps[n * 264 + u * 8];
    }
}

// ================= QKV GEMM, A-resident, balanced 3 paths =================
// grid (3, 1024): path 0=Q (A=g_x1, W=qwb), 1=K (A=g_tp, W=kvwb lo), 2=V (A=g_tp, W=kvwb hi)
#define Q2_SMEM 104448
__global__ void __launch_bounds__(256)
qkv_gemm2()
{
    extern __shared__ char sm[];
    bf* As = (bf*)sm;
    bf* Bs = (bf*)(sm + 67584);
    float* sp = (float*)(sm + 67584);     // 128 x 68 f32 = 34816 <= 36864

    const int t = threadIdx.x, w = t >> 5;
    const int path = blockIdx.x, mblk = blockIdx.y;
    const bf* Aab = (path ? g_tp : g_x1) + (size_t)mblk * 128 * 256;
    const bf* Bbase = (path == 0) ? qwb : kvwb + (path - 1) * 65536;
    const size_t tau0 = (size_t)mblk * 128;
    const int m0 = (w >> 2) * 64, n0 = (w & 3) * 32;

#pragma unroll
    for (int it = 0; it < 16; it++) {
        int idx = t + it * 256, row = idx >> 5, u = (idx & 31) * 8;
        CPA16(&As[row * 264 + u], &Aab[(size_t)row * 256 + u]);
    }
    CPCOMMIT();

#define B2LOAD(s, kc, Bb) do { \
    _Pragma("unroll") \
    for (int i_ = 0; i_ < 4; i_++) { \
        int idx_ = t + i_ * 256, row_ = idx_ >> 3, c8_ = (idx_ & 7) * 8; \
        CPA16(&Bs[(s) * 9216 + row_ * 72 + c8_], &(Bb)[(size_t)row_ * 256 + (kc) * 64 + c8_]); \
    } } while (0)

    for (int nb = 0; nb < 2; nb++) {
        const bf* Bb = Bbase + nb * 32768;
        const int nblk = path * 2 + nb;
        AccF acc[4][2];
#pragma unroll
        for (int i = 0; i < 4; i++)
#pragma unroll
            for (int j = 0; j < 2; j++) wmma::fill_fragment(acc[i][j], 0.f);

        __syncthreads();
        B2LOAD(0, 0, Bb);
        CPCOMMIT();
        for (int kc = 0; kc < 4; kc++) {
            int s = kc & 1;
            if (kc < 3) { B2LOAD(s ^ 1, kc + 1, Bb); CPCOMMIT(); CPWAIT(1); }
            else        { CPWAIT(0); }
            __syncthreads();
#pragma unroll
            for (int ks = 0; ks < 4; ks++) {
                AFrag a[4]; BCol b[2];
#pragma unroll
                for (int i = 0; i < 4; i++)
                    wmma::load_matrix_sync(a[i], As + (m0 + i * 16) * 264 + kc * 64 + ks * 16, 264);
#pragma unroll
                for (int j = 0; j < 2; j++)
                    wmma::load_matrix_sync(b[j], Bs + s * 9216 + (n0 + j * 16) * 72 + ks * 16, 72);
#pragma unroll
                for (int i = 0; i < 4; i++)
#pragma unroll
                    for (int j = 0; j < 2; j++) wmma::mma_sync(acc[i][j], a[i], b[j], acc[i][j]);
            }
            __syncthreads();
        }
#pragma unroll
        for (int half = 0; half < 2; half++) {
            if (((w & 3) >> 1) == half) {
#pragma unroll
                for (int i = 0; i < 4; i++)
#pragma unroll
                    for (int j = 0; j < 2; j++)
                        wmma::store_matrix_sync(sp + (m0 + i * 16) * 68 + (n0 - half * 64) + j * 16,
                                                acc[i][j], 68, wmma::mem_row_major);
            }
            __syncthreads();
#pragma unroll
            for (int i = 0; i < 4; i++) {
                int idx = t + i * 256, row = idx >> 3, c8 = (idx & 7) * 8;
                const float* s8 = sp + row * 68 + c8;
                uint4 v;
                v.x = pk2(s8[0], s8[1]); v.y = pk2(s8[2], s8[3]);
                v.z = pk2(s8[4], s8[5]); v.w = pk2(s8[6], s8[7]);
                *(uint4*)&g_qkv[(tau0 + row) * 768 + nblk * 128 + half * 64 + c8] = v;
            }
            __syncthreads();
        }
    }
}

// ================= per-(window,head) attention =================
// grid 8192: wi = blk>>2, head = blk&3 ; smem 45056
__global__ void __launch_bounds__(256)
attn()
{
    extern __shared__ char sm[];
    bf* qh = (bf*)sm;                 // 64 x 72 ; P aliases (Q dead after S)
    bf* ph = (bf*)sm;
    bf* kh = (bf*)(sm + 9216);
    bf* vh = (bf*)(sm + 18432);
    float* sp = (float*)(sm + 27648); // 64 x 68 f32

    const int t = threadIdx.x, w = t >> 5;
    const int h = blockIdx.x & 3;
    const size_t tau0 = (size_t)(blockIdx.x >> 2) * 64;
    const int mt = w & 3;

#pragma unroll
    for (int i = 0; i < 6; i++) {
        int idx = i * 256 + t;
        int tile = idx >> 9, rem = idx & 511;
        int r = rem >> 3, c8 = (rem & 7) * 8;
        bf* dst = (tile == 0) ? qh : (tile == 1) ? kh : vh;
        CPA16(&dst[r * 72 + c8], &g_qkv[(tau0 + r) * 768 + tile * 256 + h * 64 + c8]);
    }
    CPCOMMIT(); CPWAIT(0);
    __syncthreads();
#pragma unroll
    for (int jj = 0; jj < 2; jj++) {
        int ng = (w >> 2) * 2 + jj;
        AccF c;
        wmma::fill_fragment(c, 0.f);
#pragma unroll
        for (int k = 0; k < 4; k++) {
            AFrag a; BCol bb;
            wmma::load_matrix_sync(a, qh + mt * 16 * 72 + k * 16, 72);
            wmma::load_matrix_sync(bb, kh + ng * 16 * 72 + k * 16, 72);
            wmma::mma_sync(c, a, bb, c);
        }
        wmma::store_matrix_sync(sp + mt * 16 * 68 + ng * 16, c, 68, wmma::mem_row_major);
    }
    __syncthreads();
    {
        int row = t >> 2, part = t & 3;
        const float* sr = sp + row * 68 + part * 16;
        float v[16], mx = -1e30f;
#pragma unroll
        for (int i = 0; i < 16; i++) { v[i] = sr[i]; mx = fmaxf(mx, v[i]); }
        mx = fmaxf(mx, __shfl_xor_sync(0xffffffffu, mx, 1));
        mx = fmaxf(mx, __shfl_xor_sync(0xffffffffu, mx, 2));
        float sum = 0.f;
#pragma unroll
        for (int i = 0; i < 16; i++) { v[i] = __expf(v[i] - mx); sum += v[i]; }
        sum += __shfl_xor_sync(0xffffffffu, sum, 1);
        sum += __shfl_xor_sync(0xffffffffu, sum, 2);
        float inv = 1.f / sum;
        uint32_t* d = (uint32_t*)(ph + row * 72 + part * 16);
#pragma unroll
        for (int i = 0; i < 8; i++) d[i] = pk2(v[2 * i] * inv, v[2 * i + 1] * inv);
    }
    __syncthreads();
#pragma unroll
    for (int jj = 0; jj < 2; jj++) {
        int ng = (w >> 2) * 2 + jj;
        AccF c;
        wmma::fill_fragment(c, 0.f);
#pragma unroll
        for (int k = 0; k < 4; k++) {
            AFrag a; BRow bb;
            wmma::load_matrix_sync(a, ph + mt * 16 * 72 + k * 16, 72);
            wmma::load_matrix_sync(bb, vh + k * 16 * 72 + ng * 16, 72);
            wmma::mma_sync(c, a, bb, c);
        }
        wmma::store_matrix_sync(sp + mt * 16 * 68 + ng * 16, c, 68, wmma::mem_row_major);
    }
    __syncthreads();
#pragma unroll
    for (int i = 0; i < 2; i++) {
        int idx = i * 256 + t;
        int r = idx >> 3, c8 = (idx & 7) * 8;
        const float* s8 = sp + r * 68 + c8;
        uint4 v;
        v.x = pk2(s8[0], s8[1]); v.y = pk2(s8[2], s8[3]);
        v.z = pk2(s8[4], s8[5]); v.w = pk2(s8[6], s8[7]);
        *(uint4*)&g_o[(tau0 + r) * 256 + h * 64 + c8] = v;
    }
}

// ================= proj GEMM -> bf16 heat + BN partials =================
// grid (2, 1024); smem 86016
#define GS 9216
__global__ void __launch_bounds__(256)
proj_gemm(const float* __restrict__ feat, const float* __restrict__ fmask,
          const float* __restrict__ pb)
{
    extern __shared__ char sm[];
    bf* As = (bf*)sm;
    bf* Bs = (bf*)(sm + 36864);
    float* sp = (float*)sm;                  // col-major 128c x 136 (69632 B)
    float* bnS = (float*)(sm + 69632);
    float* bnQ = (float*)(sm + 69632 + 8192);

    const int t = threadIdx.x, w = t >> 5;
    const int nblk = blockIdx.x, mblk = blockIdx.y;
    const bf* Aab = g_o + (size_t)mblk * 128 * 256;
    const bf* Bb = pwb + nblk * 32768;

    AccF acc[4][2];
#pragma unroll
    for (int i = 0; i < 4; i++)
#pragma unroll
        for (int j = 0; j < 2; j++) wmma::fill_fragment(acc[i][j], 0.f);

#define PJ_LOAD(s, kc) do { \
    _Pragma("unroll") \
    for (int i_ = 0; i_ < 4; i_++) { \
        int idx_ = t + i_ * 256, row_ = idx_ >> 3, c8_ = (idx_ & 7) * 8; \
        CPA16(&As[(s) * GS + row_ * 72 + c8_], &Aab[(size_t)row_ * 256 + (kc) * 64 + c8_]); \
        CPA16(&Bs[(s) * GS + row_ * 72 + c8_], &Bb[(size_t)row_ * 256 + (kc) * 64 + c8_]); \
    } } while (0)

    PJ_LOAD(0, 0);
    CPCOMMIT();
    const int m0 = (w >> 2) * 64, n0 = (w & 3) * 32;
    for (int kc = 0; kc < 4; kc++) {
        int s = kc & 1;
        if (kc < 3) { PJ_LOAD(s ^ 1, kc + 1); CPCOMMIT(); CPWAIT(1); }
        else        { CPWAIT(0); }
        __syncthreads();
#pragma unroll
        for (int ks = 0; ks < 4; ks++) {
            AFrag a[4]; BCol b[2];
#pragma unroll
            for (int i = 0; i < 4; i++)
                wmma::load_matrix_sync(a[i], As + s * GS + (m0 + i * 16) * 72 + ks * 16, 72);
#pragma unroll
            for (int j = 0; j < 2; j++)
                wmma::load_matrix_sync(b[j], Bs + s * GS + (n0 + j * 16) * 72 + ks * 16, 72);
#pragma unroll
            for (int i = 0; i < 4; i++)
#pragma unroll
                for (int j = 0; j < 2; j++) wmma::mma_sync(acc[i][j], a[i], b[j], acc[i][j]);
        }
        __syncthreads();
    }
#pragma unroll
    for (int i = 0; i < 4; i++)
#pragma unroll
        for (int j = 0; j < 2; j++)
            wmma::store_matrix_sync(sp + (n0 + j * 16) * 136 + m0 + i * 16, acc[i][j],
                                    136, wmma::mem_col_major);
    __syncthreads();

    const int wi0 = mblk * 2;
    const float keep0 = g_keep[wi0], keep1 = g_keep[wi0 + 1];
    const int c0 = nblk * 128;
#pragma unroll
    for (int iter = 0; iter < 8; iter++) {
        int idx = iter * 256 + t;
        int cl = idx >> 4, wr = idx & 15, win = wr >> 3, r = wr & 7;
        int c = c0 + cl;
        int wi = wi0 + win;
        int b = wi >> 8, h0 = ((wi >> 4) & 15) * 8, w0 = (wi & 15) * 8;
        int hh = h0 + r;
        size_t g = ((size_t)(b * 256 + c) * 128 + hh) * 128 + w0;
        float keep = win ? keep1 : keep0;
        float bias = pb[c];
        const float* srow = sp + cl * 136 + win * 64 + r * 8;
        const float* fm = fmask + hh * 128 + w0;
        float s = 0.f, q = 0.f;
        bf hb[8];
#pragma unroll
        for (int e = 0; e < 8; e++) {
            hb[e] = __float2bfloat16((srow[e] + bias) * keep);
            float val = __bfloat162float(hb[e]) + feat[g + e] * fm[e];
            s += val; q += val * val;
        }
        *(uint4*)&g_x1[g] = *(uint4*)hb;   // g_x1 reused as heat (BCHW bf16)
        bnS[cl * 16 + wr] = s;
        bnQ[cl * 16 + wr] = q;
    }
    __syncthreads();
    if (t < 128) {
        float s = 0.f, q = 0.f;
#pragma unroll
        for (int m = 0; m < 16; m++) { s += bnS[t * 16 + m]; q += bnQ[t * 16 + m]; }
        g_ps[(size_t)(c0 + t) * 1024 + mblk] = s;
        g_pq[(size_t)(c0 + t) * 1024 + mblk] = q;
    }
}

// ================= BN finalize + apply =================
__global__ void bn_fin(const float* __restrict__ gamma, const float* __restrict__ beta) {
    __shared__ float rs[256], rq[256];
    const int c = blockIdx.x, t = threadIdx.x;
    float s = 0.f, q = 0.f;
    for (int i = t; i < 1024; i += 256) {
        s += g_ps[c * 1024 + i];
        q += g_pq[c * 1024 + i];
    }
    rs[t] = s; rq[t] = q;
    __syncthreads();
    for (int o = 128; o > 0; o >>= 1) {
        if (t < o) { rs[t] += rs[t + o]; rq[t] += rq[t + o]; }
        __syncthreads();
    }
    if (t == 0) {
        const float inv_n = 1.f / 131072.f;
        float mean = rs[0] * inv_n;
        float var = rq[0] * inv_n - mean * mean;
        float sc = gamma[c] * rsqrtf(var + 1e-5f);
        g_scale[c] = sc;
        g_shift[c] = beta[c] - mean * sc;
    }
}

__global__ void bn_apply(const float* __restrict__ feat, const float* __restrict__ fmask,
                         float* __restrict__ out) {
    int i = blockIdx.x * blockDim.x + threadIdx.x;   // over 8,388,608 float4
    int c = (i >> 12) & 255;
    int p = i & 4095;
    float sc = g_scale[c], sh = g_shift[c];
    float4 fm = ((const float4*)fmask)[p];
    float4 f  = ((const float4*)feat)[i];
    uint2 hu = ((const uint2*)g_x1)[i];
    __nv_bfloat162 h01 = *(__nv_bfloat162*)&hu.x;
    __nv_bfloat162 h23 = *(__nv_bfloat162*)&hu.y;
    float4 v;
    v.x = (__bfloat162float(h01.x) + f.x * fm.x) * sc + sh;
    v.y = (__bfloat162float(h01.y) + f.y * fm.y) * sc + sh;
    v.z = (__bfloat162float(h23.x) + f.z * fm.z) * sc + sh;
    v.w = (__bfloat162float(h23.y) + f.w * fm.w) * sc + sh;
    ((float4*)out)[i] = v;
}

// ================= launch =================
extern "C" void kernel_launch(void* const* d_in, const int* in_sizes, int n_in,
                              void* d_out, int out_size)
{
    const float* pre   = (const float*)d_in[0];
    const float* pmask = (const float*)d_in[1];
    const float* feat  = (const float*)d_in[2];
    const float* fmask = (const float*)d_in[3];
    const float* mask  = (const float*)d_in[4];
    const float* qw    = (const float*)d_in[5];
    const float* kvw   = (const float*)d_in[6];
    const float* pw    = (const float*)d_in[7];
    const float* pb    = (const float*)d_in[8];
    const float* gamma = (const float*)d_in[9];
    const float* beta  = (const float*)d_in[10];
    float* out = (float*)d_out;

    cudaFuncSetAttribute(prep, cudaFuncAttributeMaxDynamicSharedMemorySize, 68352);
    cudaFuncSetAttribute(qkv_gemm2, cudaFuncAttributeMaxDynamicSharedMemorySize, Q2_SMEM);
    cudaFuncSetAttribute(attn, cudaFuncAttributeMaxDynamicSharedMemorySize, 45056);
    cudaFuncSetAttribute(proj_gemm, cudaFuncAttributeMaxDynamicSharedMemorySize, 86016);

    wconv<<<512, 256>>>(qw, kvw, pw);
    prep<<<2048, 256, 68352>>>(pre, pmask, feat, fmask, mask);
    qkv_gemm2<<<dim3(3, 1024), 256, Q2_SMEM>>>();
    attn<<<8192, 256, 45056>>>();
    proj_gemm<<<dim3(2, 1024), 256, 86016>>>(feat, fmask, pb);
    bn_fin<<<256, 256>>>(gamma, beta);
    bn_apply<<<32768, 256>>>(feat, fmask, out);
}